// round 5
// baseline (speedup 1.0000x reference)
#include <cuda_runtime.h>

#define BATCH   8
#define NP1     1024
#define DP1     128
#define NLAYER  4
#define NHEAD   8
#define NTOK    1023
#define DSMALL  127
#define NB      128      // grid size (must be <= #SMs for residency)

// ---------------------------------------------------------------------------
// Global scratch
// ---------------------------------------------------------------------------
__device__ __align__(16) float g_PB[NLAYER][NHEAD][DP1][DP1]; // PB[l][h][a][b] = Pfull[b][a]
__device__ __align__(16) float g_QT[NLAYER][NHEAD][DP1][DP1]; // QT[l][h][k][i] = Qfull[i][k]
__device__ __align__(16) float g_G [BATCH][DP1][DP1];
__device__ __align__(16) float g_Gt[BATCH][DP1][DP1];
__device__ __align__(16) float g_R [2][BATCH][DP1][DP1];      // layer-parity ping-pong
__device__ __align__(16) float g_W [2][BATCH][DP1][DP1];      // W = M^T ping-pong

// Grid barrier state (reset every call by reset_kernel)
__device__ volatile unsigned g_bar_gen;
__device__ unsigned          g_bar_cnt;

__global__ void reset_kernel() {
    g_bar_cnt = 0;
    g_bar_gen = 0;
}

// Monotonic-generation grid barrier. All NB blocks resident -> deadlock-free.
__device__ __forceinline__ void gbar(unsigned& gen) {
    __syncthreads();
    unsigned target = ++gen;             // all threads track the same gen
    if (threadIdx.x == 0) {
        __threadfence();                 // release prior writes
        unsigned old = atomicAdd(&g_bar_cnt, 1u);
        if (old == NB - 1) {
            g_bar_cnt = 0;
            __threadfence();
            g_bar_gen = target;          // volatile store
        } else {
            while (g_bar_gen < target) __nanosleep(64);
        }
        __threadfence();                 // acquire
    }
    __syncthreads();
}

// ---------------------------------------------------------------------------
// The megakernel. 128 blocks x 256 threads, ~42KB static smem (1 block/SM).
// ---------------------------------------------------------------------------
__global__ __launch_bounds__(256, 1)
void mega_kernel(const float* __restrict__ Zin,
                 const float* __restrict__ allparam,
                 float* __restrict__ Zout) {
    __shared__ __align__(16) float smem[10752];   // 42 KB union
    const int bid = blockIdx.x;
    const int tid = threadIdx.x;
    unsigned gen = 0;

    // ======================= Stage 0: pad params + init ====================
    {
        // pad: 4*8*128*128 = 524288 elems -> 4096 per block, 16 per thread
#pragma unroll
        for (int q = 0; q < 16; q++) {
            int idx = bid * 4096 + q * 256 + tid;
            int bb = idx & 127;
            int a  = (idx >> 7) & 127;
            int h  = (idx >> 14) & 7;
            int l  = idx >> 17;
            float pv = 0.0f, qv = 0.0f;
            if (bb < DSMALL && a < DSMALL) {
                const float* base = allparam
                    + ((((size_t)l * NHEAD + h) * 2 + 0) * DSMALL + bb) * DSMALL + a;
                pv = base[0];
                qv = base[DSMALL * DSMALL];
            }
            if (bb == DSMALL && a == DSMALL) pv = 1.0f;
            g_PB[l][h][a][bb] = pv;
            g_QT[l][h][a][bb] = qv;
        }
        // init: G = 0, W[0] = I, R[0] = 0 (131072 elems -> 1024/block)
#pragma unroll
        for (int q = 0; q < 4; q++) {
            int idx = bid * 1024 + q * 256 + tid;
            int b = idx >> 14, i = (idx >> 7) & 127, j = idx & 127;
            g_G[b][i][j] = 0.0f;
            g_W[0][b][i][j] = (i == j) ? 1.0f : 0.0f;
            g_R[0][b][i][j] = 0.0f;
        }
    }
    gbar(gen);

    // ======================= Stage 1: Gram =================================
    // block (b = bid>>4, s = bid&15): G[b] += Zslab^T Zslab, rows [s*64, s*64+64)
    {
        const int b = bid >> 4, s = bid & 15;
        const int tx = tid & 15, ty = tid >> 4;
        float* Zs = smem;   // [64][128] = 8192
        const float* Zb = Zin + (size_t)b * NP1 * DP1;
        const int m0 = s * 64;
#pragma unroll
        for (int q = 0; q < 8; q++) {
            int f = tid + q * 256;
            int row = f >> 5, c4 = f & 31;
            int m = m0 + row;
            float4 v = make_float4(0.f, 0.f, 0.f, 0.f);
            if (m < NTOK) v = *(const float4*)&Zb[(size_t)m * DP1 + c4 * 4];
            *(float4*)&Zs[row * DP1 + c4 * 4] = v;
        }
        __syncthreads();

        float acc[8][8];
#pragma unroll
        for (int i = 0; i < 8; i++)
#pragma unroll
            for (int j = 0; j < 8; j++) acc[i][j] = 0.0f;

#pragma unroll 4
        for (int kk = 0; kk < 64; kk++) {
            float4 a0 = *(const float4*)&Zs[kk * DP1 + ty * 8];
            float4 a1 = *(const float4*)&Zs[kk * DP1 + ty * 8 + 4];
            float4 b0 = *(const float4*)&Zs[kk * DP1 + tx * 8];
            float4 b1 = *(const float4*)&Zs[kk * DP1 + tx * 8 + 4];
            float a_[8] = {a0.x, a0.y, a0.z, a0.w, a1.x, a1.y, a1.z, a1.w};
            float b_[8] = {b0.x, b0.y, b0.z, b0.w, b1.x, b1.y, b1.z, b1.w};
#pragma unroll
            for (int i = 0; i < 8; i++)
#pragma unroll
                for (int j = 0; j < 8; j++) acc[i][j] = fmaf(a_[i], b_[j], acc[i][j]);
        }

        float* Gb = &g_G[b][0][0];
#pragma unroll
        for (int i = 0; i < 8; i++)
#pragma unroll
            for (int j = 0; j < 8; j++)
                atomicAdd(&Gb[(ty * 8 + i) * DP1 + tx * 8 + j], acc[i][j]);
    }
    gbar(gen);

    // ======================= Layer loop ====================================
    for (int l = 0; l < NLAYER; l++) {
        const int cur = l & 1, nxt = (l + 1) & 1;

        // ---- TR stage: block (b, h, s) -----------------------------------
        // phase1: Ts = G[b] @ PB[l][h][:, s*64 .. +64)   (smem, 128x64)
        // phase2: R[cur][b][:, slice] += (1/N) * Q_h @ Ts  (atomic)
        {
            const int b = bid >> 4, h = (bid >> 1) & 7, s = bid & 1;
            const int c0 = s * 64;
            const int tx = tid & 15, ty = tid >> 4;
            float* Ts  = smem;            // [128][68] = 8704 (written after phase1)
            float* As1 = smem;            // [2][16][128] = 4096 (aliases Ts)
            float* Bs1 = smem + 4096;     // [2][16][64]  = 2048
            float* As2 = smem + 8704;     // [16][128]    = 2048

            const float* Gb = &g_G[b][0][0];
            const float* PB = &g_PB[l][h][0][0];
            const float* QT = &g_QT[l][h][0][0];

            const int ar = tid >> 5, ac = (tid & 31) * 4;  // A rows {ar, ar+8}
            const int br = tid >> 4, bc = (tid & 15) * 4;  // B row br

            // ---- phase 1 ----
            float4 ra0 = __ldcg((const float4*)&Gb[ar * DP1 + ac]);
            float4 ra1 = __ldcg((const float4*)&Gb[(ar + 8) * DP1 + ac]);
            float4 rb  = __ldg((const float4*)&PB[br * DP1 + c0 + bc]);
            *(float4*)&As1[ar * DP1 + ac] = ra0;
            *(float4*)&As1[(ar + 8) * DP1 + ac] = ra1;
            *(float4*)&Bs1[br * 64 + bc] = rb;
            __syncthreads();

            float acc[8][4];
#pragma unroll
            for (int i = 0; i < 8; i++)
#pragma unroll
                for (int j = 0; j < 4; j++) acc[i][j] = 0.0f;

            for (int t = 0; t < 8; t++) {
                const int cb = t & 1;
                if (t < 7) {
                    int k0 = (t + 1) * 16;
                    ra0 = __ldcg((const float4*)&Gb[(k0 + ar) * DP1 + ac]);
                    ra1 = __ldcg((const float4*)&Gb[(k0 + 8 + ar) * DP1 + ac]);
                    rb  = __ldg((const float4*)&PB[(k0 + br) * DP1 + c0 + bc]);
                }
                const float* Ac = As1 + cb * 2048;
                const float* Bc = Bs1 + cb * 1024;
                float4 a0 = *(const float4*)&Ac[ty * 8];
                float4 a1 = *(const float4*)&Ac[ty * 8 + 4];
                float4 bv = *(const float4*)&Bc[tx * 4];
#pragma unroll
                for (int kk = 0; kk < 16; kk++) {
                    float4 na0, na1, nbv;
                    if (kk < 15) {
                        na0 = *(const float4*)&Ac[(kk + 1) * DP1 + ty * 8];
                        na1 = *(const float4*)&Ac[(kk + 1) * DP1 + ty * 8 + 4];
                        nbv = *(const float4*)&Bc[(kk + 1) * 64 + tx * 4];
                    }
                    float a_[8] = {a0.x, a0.y, a0.z, a0.w, a1.x, a1.y, a1.z, a1.w};
                    float b_[4] = {bv.x, bv.y, bv.z, bv.w};
#pragma unroll
                    for (int i = 0; i < 8; i++)
#pragma unroll
                        for (int j = 0; j < 4; j++) acc[i][j] = fmaf(a_[i], b_[j], acc[i][j]);
                    a0 = na0; a1 = na1; bv = nbv;
                }
                if (t < 7) {
                    const int nb2 = cb ^ 1;
                    *(float4*)&As1[nb2 * 2048 + ar * DP1 + ac] = ra0;
                    *(float4*)&As1[nb2 * 2048 + (ar + 8) * DP1 + ac] = ra1;
                    *(float4*)&Bs1[nb2 * 1024 + br * 64 + bc] = rb;
                    __syncthreads();
                }
            }
            __syncthreads();   // staging dead; write Ts over it
#pragma unroll
            for (int i = 0; i < 8; i++)
                *(float4*)&Ts[(ty * 8 + i) * 68 + tx * 4] =
                    make_float4(acc[i][0], acc[i][1], acc[i][2], acc[i][3]);

            // ---- phase 2: Rpart = Q_h @ Ts ----
            float acc2[8][4];
#pragma unroll
            for (int i = 0; i < 8; i++)
#pragma unroll
                for (int j = 0; j < 4; j++) acc2[i][j] = 0.0f;

            for (int t = 0; t < 8; t++) {
                __syncthreads();
                int k0 = t * 16;
                *(float4*)&As2[ar * DP1 + ac] =
                    __ldg((const float4*)&QT[(k0 + ar) * DP1 + ac]);
                *(float4*)&As2[(ar + 8) * DP1 + ac] =
                    __ldg((const float4*)&QT[(k0 + ar + 8) * DP1 + ac]);
                __syncthreads();
                float4 a0 = *(const float4*)&As2[ty * 8];
                float4 a1 = *(const float4*)&As2[ty * 8 + 4];
                float4 bv = *(const float4*)&Ts[k0 * 68 + tx * 4];
#pragma unroll
                for (int kk = 0; kk < 16; kk++) {
                    float4 na0, na1, nbv;
                    if (kk < 15) {
                        na0 = *(const float4*)&As2[(kk + 1) * DP1 + ty * 8];
                        na1 = *(const float4*)&As2[(kk + 1) * DP1 + ty * 8 + 4];
                        nbv = *(const float4*)&Ts[(k0 + kk + 1) * 68 + tx * 4];
                    }
                    float a_[8] = {a0.x, a0.y, a0.z, a0.w, a1.x, a1.y, a1.z, a1.w};
                    float b_[4] = {bv.x, bv.y, bv.z, bv.w};
#pragma unroll
                    for (int i = 0; i < 8; i++)
#pragma unroll
                        for (int j = 0; j < 4; j++) acc2[i][j] = fmaf(a_[i], b_[j], acc2[i][j]);
                    a0 = na0; a1 = na1; bv = nbv;
                }
            }
            const float invN = 1.0f / (float)NTOK;
            float* Rb = &g_R[cur][b][0][0];
#pragma unroll
            for (int i = 0; i < 8; i++)
#pragma unroll
                for (int j = 0; j < 4; j++)
                    atomicAdd(&Rb[(ty * 8 + i) * DP1 + c0 + tx * 4 + j],
                              acc2[i][j] * invN);
        }
        gbar(gen);

        // ---- c1 stage: Gt = G + G@R  (op0) ;  W' = W + R^T@W (op1) --------
        // block (b = bid>>4, t5 = bid&15): op=t5>>3, tile 64x32
        {
            const int b = bid >> 4, t5 = bid & 15;
            const int op = t5 >> 3, sub = t5 & 7;
            const int i0 = (sub >> 2) * 64, c0 = (sub & 3) * 32;
            const int tx = tid & 7, ty = tid >> 3;   // cols tx*4 (32), rows ty*2 (64)
            float* As = smem;          // [16][64]
            float* Bs = smem + 1024;   // [16][32]

            const float* Rc = &g_R[cur][0][0][0] + (size_t)b * DP1 * DP1;
            const bool skip = (l == NLAYER - 1 && op == 0);  // Gt unused on last layer

            if (!skip) {
                const float* Asrc = op ? Rc : &g_G[b][0][0];
                const float* Bsrc = op ? &g_W[cur][b][0][0] : Rc;
                const float* base = op ? &g_W[cur][b][0][0] : &g_G[b][0][0];
                float* dst = op ? &g_W[nxt][b][0][0] : &g_Gt[b][0][0];

                float acc[2][4] = {{0.f,0.f,0.f,0.f},{0.f,0.f,0.f,0.f}};
                const int asr = tid >> 4, asc = (tid & 15) * 4;
                for (int t = 0; t < 8; t++) {
                    __syncthreads();
                    int k0 = t * 16;
                    *(float4*)&As[asr * 64 + asc] =
                        __ldcg((const float4*)&Asrc[(k0 + asr) * DP1 + i0 + asc]);
                    if (tid < 128)
                        *(float4*)&Bs[(tid >> 3) * 32 + (tid & 7) * 4] =
                            __ldcg((const float4*)&Bsrc[(k0 + (tid >> 3)) * DP1 + c0 + (tid & 7) * 4]);
                    __syncthreads();
#pragma unroll
                    for (int kk = 0; kk < 16; kk++) {
                        float a0 = As[kk * 64 + ty * 2];
                        float a1 = As[kk * 64 + ty * 2 + 1];
                        float4 bv = *(const float4*)&Bs[kk * 32 + tx * 4];
                        acc[0][0] = fmaf(a0, bv.x, acc[0][0]);
                        acc[0][1] = fmaf(a0, bv.y, acc[0][1]);
                        acc[0][2] = fmaf(a0, bv.z, acc[0][2]);
                        acc[0][3] = fmaf(a0, bv.w, acc[0][3]);
                        acc[1][0] = fmaf(a1, bv.x, acc[1][0]);
                        acc[1][1] = fmaf(a1, bv.y, acc[1][1]);
                        acc[1][2] = fmaf(a1, bv.z, acc[1][2]);
                        acc[1][3] = fmaf(a1, bv.w, acc[1][3]);
                    }
                }
#pragma unroll
                for (int i = 0; i < 2; i++) {
                    int row = i0 + ty * 2 + i;
                    float4 b4 = __ldcg((const float4*)&base[row * DP1 + c0 + tx * 4]);
                    *(float4*)&dst[row * DP1 + c0 + tx * 4] =
                        make_float4(b4.x + acc[i][0], b4.y + acc[i][1],
                                    b4.z + acc[i][2], b4.w + acc[i][3]);
                }
            }
            // zero next-parity R (safe: R[nxt] not in use this layer)
            float* Rn = &g_R[nxt][0][0][0];
#pragma unroll
            for (int k = 0; k < 4; k++)
                Rn[bid * 1024 + k * 256 + tid] = 0.0f;
        }
        gbar(gen);

        // ---- c2 stage: G = Gt + R^T @ Gt (skipped on last layer) ----------
        if (l < NLAYER - 1) {
            const int b = bid >> 4, t5 = bid & 15;
            const int i0 = (t5 >> 2) * 32, c0 = (t5 & 3) * 32;
            const int tx = tid & 7, ty = tid >> 3;   // cols tx*4 (32), row ty (32)
            float* As = smem;          // [16][32]
            float* Bs = smem + 512;    // [16][32]
            const float* Rc = &g_R[cur][0][0][0] + (size_t)b * DP1 * DP1;
            const float* Gt = &g_Gt[b][0][0];

            float acc[4] = {0.f, 0.f, 0.f, 0.f};
            for (int t = 0; t < 8; t++) {
                __syncthreads();
                int k0 = t * 16;
                if (tid < 128) {
                    *(float4*)&As[(tid >> 3) * 32 + (tid & 7) * 4] =
                        __ldcg((const float4*)&Rc[(k0 + (tid >> 3)) * DP1 + i0 + (tid & 7) * 4]);
                } else {
                    int u = tid - 128;
                    *(float4*)&Bs[(u >> 3) * 32 + (u & 7) * 4] =
                        __ldcg((const float4*)&Gt[(k0 + (u >> 3)) * DP1 + c0 + (u & 7) * 4]);
                }
                __syncthreads();
#pragma unroll
                for (int kk = 0; kk < 16; kk++) {
                    float a = As[kk * 32 + ty];
                    float4 bv = *(const float4*)&Bs[kk * 32 + tx * 4];
                    acc[0] = fmaf(a, bv.x, acc[0]);
                    acc[1] = fmaf(a, bv.y, acc[1]);
                    acc[2] = fmaf(a, bv.z, acc[2]);
                    acc[3] = fmaf(a, bv.w, acc[3]);
                }
            }
            int row = i0 + ty;
            float4 b4 = __ldcg((const float4*)&Gt[row * DP1 + c0 + tx * 4]);
            *(float4*)&g_G[b][row][c0 + tx * 4] =
                make_float4(b4.x + acc[0], b4.y + acc[1], b4.z + acc[2], b4.w + acc[3]);
            gbar(gen);
        }
    }

    // ======================= Final: Zout = Zin @ M  (M^T = W[0]) ==========
    {
        const int b = bid >> 4, rt = bid & 15;
        const int n0 = rt * 64;
        const int tx = tid & 15, ty = tid >> 4;
        float* As = smem;          // [2][16][68]  = 2176
        float* Bs = smem + 2176;   // [2][16][132] = 4224

        const float* Zb = Zin + (size_t)b * NP1 * DP1;
        float* Zo = Zout + (size_t)b * NP1 * DP1;
        const float* Wb = &g_W[0][b][0][0];

        const int arow = tid >> 2, aq = tid & 3;
        const int brow = tid >> 2, bq = tid & 3;

        float4 va, vb0, vb1;
        va  = *(const float4*)&Zb[(size_t)(n0 + arow) * DP1 + aq * 4];
        vb0 = __ldcg((const float4*)&Wb[brow * DP1 + bq * 4]);
        vb1 = __ldcg((const float4*)&Wb[(brow + 64) * DP1 + bq * 4]);
        {
            As[(aq * 4 + 0) * 68 + arow] = va.x;  As[(aq * 4 + 1) * 68 + arow] = va.y;
            As[(aq * 4 + 2) * 68 + arow] = va.z;  As[(aq * 4 + 3) * 68 + arow] = va.w;
            Bs[(bq * 4 + 0) * 132 + brow] = vb0.x; Bs[(bq * 4 + 1) * 132 + brow] = vb0.y;
            Bs[(bq * 4 + 2) * 132 + brow] = vb0.z; Bs[(bq * 4 + 3) * 132 + brow] = vb0.w;
            Bs[(bq * 4 + 0) * 132 + brow + 64] = vb1.x; Bs[(bq * 4 + 1) * 132 + brow + 64] = vb1.y;
            Bs[(bq * 4 + 2) * 132 + brow + 64] = vb1.z; Bs[(bq * 4 + 3) * 132 + brow + 64] = vb1.w;
        }
        __syncthreads();

        float acc[4][8];
#pragma unroll
        for (int i = 0; i < 4; i++)
#pragma unroll
            for (int j = 0; j < 8; j++) acc[i][j] = 0.0f;

        for (int t = 0; t < 8; t++) {
            const int cb = t & 1;
            if (t < 7) {
                int k0 = (t + 1) * 16;
                va  = *(const float4*)&Zb[(size_t)(n0 + arow) * DP1 + k0 + aq * 4];
                vb0 = __ldcg((const float4*)&Wb[brow * DP1 + k0 + bq * 4]);
                vb1 = __ldcg((const float4*)&Wb[(brow + 64) * DP1 + k0 + bq * 4]);
            }
            const float* Ac = As + cb * 1088;
            const float* Bc = Bs + cb * 2112;
#pragma unroll
            for (int kk = 0; kk < 16; kk++) {
                float4 av = *(const float4*)&Ac[kk * 68 + ty * 4];
                float4 b0 = *(const float4*)&Bc[kk * 132 + tx * 8];
                float4 b1 = *(const float4*)&Bc[kk * 132 + tx * 8 + 4];
                float a_[4] = {av.x, av.y, av.z, av.w};
                float b_[8] = {b0.x, b0.y, b0.z, b0.w, b1.x, b1.y, b1.z, b1.w};
#pragma unroll
                for (int i = 0; i < 4; i++)
#pragma unroll
                    for (int j = 0; j < 8; j++) acc[i][j] = fmaf(a_[i], b_[j], acc[i][j]);
            }
            if (t < 7) {
                const int nb2 = cb ^ 1;
                As[nb2 * 1088 + (aq * 4 + 0) * 68 + arow] = va.x;
                As[nb2 * 1088 + (aq * 4 + 1) * 68 + arow] = va.y;
                As[nb2 * 1088 + (aq * 4 + 2) * 68 + arow] = va.z;
                As[nb2 * 1088 + (aq * 4 + 3) * 68 + arow] = va.w;
                Bs[nb2 * 2112 + (bq * 4 + 0) * 132 + brow] = vb0.x;
                Bs[nb2 * 2112 + (bq * 4 + 1) * 132 + brow] = vb0.y;
                Bs[nb2 * 2112 + (bq * 4 + 2) * 132 + brow] = vb0.z;
                Bs[nb2 * 2112 + (bq * 4 + 3) * 132 + brow] = vb0.w;
                Bs[nb2 * 2112 + (bq * 4 + 0) * 132 + brow + 64] = vb1.x;
                Bs[nb2 * 2112 + (bq * 4 + 1) * 132 + brow + 64] = vb1.y;
                Bs[nb2 * 2112 + (bq * 4 + 2) * 132 + brow + 64] = vb1.z;
                Bs[nb2 * 2112 + (bq * 4 + 3) * 132 + brow + 64] = vb1.w;
                __syncthreads();
            }
        }

#pragma unroll
        for (int i = 0; i < 4; i++) {
            size_t off = (size_t)(n0 + ty * 4 + i) * DP1 + tx * 8;
            *(float4*)&Zo[off]     = make_float4(acc[i][0], acc[i][1], acc[i][2], acc[i][3]);
            *(float4*)&Zo[off + 4] = make_float4(acc[i][4], acc[i][5], acc[i][6], acc[i][7]);
        }
    }
}

// ---------------------------------------------------------------------------
extern "C" void kernel_launch(void* const* d_in, const int* in_sizes, int n_in,
                              void* d_out, int out_size) {
    const float* Z_in     = (const float*)d_in[0];
    const float* allparam = (const float*)d_in[1];
    float* Z_out = (float*)d_out;

    reset_kernel<<<1, 1>>>();
    mega_kernel<<<NB, 256>>>(Z_in, allparam, Z_out);
}

// round 6
// speedup vs baseline: 1.0374x; 1.0374x over previous
#include <cuda_runtime.h>
#include <mma.h>
using namespace nvcuda;

#define BATCH   8
#define NP1     1024
#define DP1     128
#define NLAYER  4
#define NHEAD   8
#define NTOK    1023
#define DSMALL  127

// ---------------------------------------------------------------------------
// g_PB[l][h][a][b] = Pfull[b][a]   (P^T, padded; corner Pfull[127][127]=1)
// g_QT[l][h][k][i] = Qfull[i][k]   (Q^T, zero padded)
// g_G [b]      : Gram (symmetric), per layer G <- (I+R)^T G (I+R)
// g_Gt[b]      : Gtmp = G (I+R)
// g_R [p][b]   : R_l, layer-parity ping-pong (zeroed one layer ahead by c1)
// g_W [p][b]   : W = M^T ping-pong, W' = W + R^T W  (I included)
// ---------------------------------------------------------------------------
__device__ __align__(16) float g_PB[NLAYER][NHEAD][DP1][DP1];
__device__ __align__(16) float g_QT[NLAYER][NHEAD][DP1][DP1];
__device__ __align__(16) float g_G [BATCH][DP1][DP1];
__device__ __align__(16) float g_Gt[BATCH][DP1][DP1];
__device__ __align__(16) float g_R [2][BATCH][DP1][DP1];
__device__ __align__(16) float g_W [2][BATCH][DP1][DP1];

// ---------------------------------------------------------------------------
__global__ void pad_params_kernel(const float* __restrict__ allparam) {
    int idx = blockIdx.x * blockDim.x + threadIdx.x;
    const int total = NLAYER * NHEAD * DP1 * DP1;
    if (idx >= total) return;
    int bb = idx & 127;
    int a  = (idx >> 7) & 127;
    int h  = (idx >> 14) & 7;
    int l  = idx >> 17;

    float pv = 0.0f, qv = 0.0f;
    if (bb < DSMALL && a < DSMALL) {
        const float* base = allparam
            + ((((size_t)l * NHEAD + h) * 2 + 0) * DSMALL + bb) * DSMALL + a;
        pv = base[0];
        qv = base[DSMALL * DSMALL];
    }
    if (bb == DSMALL && a == DSMALL) pv = 1.0f;

    g_PB[l][h][a][bb] = pv;
    g_QT[l][h][a][bb] = qv;
}

__global__ void init_kernel() {
    int idx = blockIdx.x * blockDim.x + threadIdx.x;   // < 8*128*128
    int j = idx & 127, i = (idx >> 7) & 127, b = idx >> 14;
    g_G[b][i][j] = 0.0f;
    g_R[0][b][i][j] = 0.0f;
    g_W[0][b][i][j] = (i == j) ? 1.0f : 0.0f;
}

// ---------------------------------------------------------------------------
// Gram: G[b] += Zslab^T Zslab over rows [s*64, s*64+64) ∩ [0,1023)
// ---------------------------------------------------------------------------
__global__ __launch_bounds__(256) void gram_kernel(const float* __restrict__ Z) {
    const int b = blockIdx.x, s = blockIdx.y;
    const int tid = threadIdx.x, tx = tid & 15, ty = tid >> 4;
    __shared__ __align__(16) float Zs[64][DP1];

    const float* Zb = Z + (size_t)b * NP1 * DP1;
    const int m0 = s * 64;
#pragma unroll
    for (int q = 0; q < 8; q++) {
        int f = tid + q * 256;
        int row = f >> 5, c4 = f & 31;
        int m = m0 + row;
        float4 v = make_float4(0.f, 0.f, 0.f, 0.f);
        if (m < NTOK) v = *(const float4*)&Zb[(size_t)m * DP1 + c4 * 4];
        *(float4*)&Zs[row][c4 * 4] = v;
    }
    __syncthreads();

    float acc[8][8];
#pragma unroll
    for (int i = 0; i < 8; i++)
#pragma unroll
        for (int j = 0; j < 8; j++) acc[i][j] = 0.0f;

#pragma unroll 8
    for (int kk = 0; kk < 64; kk++) {
        float4 a0 = *(const float4*)&Zs[kk][ty * 8];
        float4 a1 = *(const float4*)&Zs[kk][ty * 8 + 4];
        float4 b0 = *(const float4*)&Zs[kk][tx * 8];
        float4 b1 = *(const float4*)&Zs[kk][tx * 8 + 4];
        float a_[8] = {a0.x, a0.y, a0.z, a0.w, a1.x, a1.y, a1.z, a1.w};
        float b_[8] = {b0.x, b0.y, b0.z, b0.w, b1.x, b1.y, b1.z, b1.w};
#pragma unroll
        for (int i = 0; i < 8; i++)
#pragma unroll
            for (int j = 0; j < 8; j++) acc[i][j] = fmaf(a_[i], b_[j], acc[i][j]);
    }

    float* Gb = &g_G[b][0][0];
#pragma unroll
    for (int i = 0; i < 8; i++)
#pragma unroll
        for (int j = 0; j < 8; j++)
            atomicAdd(&Gb[(ty * 8 + i) * DP1 + tx * 8 + j], acc[i][j]);
}

// ---------------------------------------------------------------------------
// Fused TR kernel (tf32 wmma). Block (b, h, s): slice cols [s*64, s*64+64).
//   Phase 1: Ts = G[b] @ PB[l][h][:, slice]        (wmma, -> smem)
//   Phase 2: R[p][b][:, slice] += (1/N) Q_h @ Ts   (wmma, atomic out)
// 8 warps; warp w owns rows [16w, 16w+16). 256 threads.
// ---------------------------------------------------------------------------
__global__ __launch_bounds__(256) void tr_kernel(int layer, int p) {
    const int b = blockIdx.x, h = blockIdx.y, s = blockIdx.z;
    const int c0 = s * 64;
    const int tid = threadIdx.x;
    const int w = tid >> 5;

    __shared__ __align__(16) float Ts[128][72];   // 36 KB

    const float* Gb = &g_G[b][0][0];
    const float* PB = &g_PB[layer][h][0][0];
    const float* QT = &g_QT[layer][h][0][0];

    // ---- Phase 1: Ts[band] = G[band] @ PB[:, c0:c0+64] ----
    {
        wmma::fragment<wmma::accumulator, 16, 16, 8, float> c[4];
#pragma unroll
        for (int j = 0; j < 4; j++) wmma::fill_fragment(c[j], 0.0f);

        for (int k0 = 0; k0 < DP1; k0 += 8) {
            wmma::fragment<wmma::matrix_a, 16, 16, 8, wmma::precision::tf32,
                           wmma::row_major> a;
            wmma::load_matrix_sync(a, Gb + (w * 16) * DP1 + k0, DP1);
#pragma unroll
            for (int t = 0; t < a.num_elements; t++)
                a.x[t] = wmma::__float_to_tf32(a.x[t]);
#pragma unroll
            for (int j = 0; j < 4; j++) {
                wmma::fragment<wmma::matrix_b, 16, 16, 8, wmma::precision::tf32,
                               wmma::row_major> bf;
                wmma::load_matrix_sync(bf, PB + k0 * DP1 + c0 + j * 16, DP1);
#pragma unroll
                for (int t = 0; t < bf.num_elements; t++)
                    bf.x[t] = wmma::__float_to_tf32(bf.x[t]);
                wmma::mma_sync(c[j], a, bf, c[j]);
            }
        }
#pragma unroll
        for (int j = 0; j < 4; j++)
            wmma::store_matrix_sync(&Ts[w * 16][j * 16], c[j], 72,
                                    wmma::mem_row_major);
    }
    __syncthreads();

    // ---- Phase 2: Rband = Q[band] @ Ts ----
    {
        wmma::fragment<wmma::accumulator, 16, 16, 8, float> c[4];
#pragma unroll
        for (int j = 0; j < 4; j++) wmma::fill_fragment(c[j], 0.0f);

        for (int k0 = 0; k0 < DP1; k0 += 8) {
            // A = Q[band][k] = QT[k][band] -> col_major load, ldm 128
            wmma::fragment<wmma::matrix_a, 16, 16, 8, wmma::precision::tf32,
                           wmma::col_major> a;
            wmma::load_matrix_sync(a, QT + k0 * DP1 + w * 16, DP1);
#pragma unroll
            for (int t = 0; t < a.num_elements; t++)
                a.x[t] = wmma::__float_to_tf32(a.x[t]);
#pragma unroll
            for (int j = 0; j < 4; j++) {
                wmma::fragment<wmma::matrix_b, 16, 16, 8, wmma::precision::tf32,
                               wmma::row_major> bf;
                wmma::load_matrix_sync(bf, &Ts[k0][j * 16], 72);
#pragma unroll
                for (int t = 0; t < bf.num_elements; t++)
                    bf.x[t] = wmma::__float_to_tf32(bf.x[t]);
                wmma::mma_sync(c[j], a, bf, c[j]);
            }
        }
        __syncthreads();   // all Ts reads done; reuse Ts as staging
#pragma unroll
        for (int j = 0; j < 4; j++)
            wmma::store_matrix_sync(&Ts[w * 16][j * 16], c[j], 72,
                                    wmma::mem_row_major);
    }
    __syncthreads();

    // ---- atomic accumulate into g_R[p][b][:, slice] ----
    const float invN = 1.0f / (float)NTOK;
    float* Rb = &g_R[p][b][0][0];
    // 128x64 elems, 256 threads -> 32 each (row = f>>4, col4 = f&15)
#pragma unroll
    for (int q = 0; q < 8; q++) {
        int f = tid + q * 256;            // 0..2047 (float4 units)
        int row = f >> 4, c4 = (f & 15) * 4;
        float4 v = *(const float4*)&Ts[row][c4];
        float* dst = &Rb[row * DP1 + c0 + c4];
        atomicAdd(dst + 0, v.x * invN);
        atomicAdd(dst + 1, v.y * invN);
        atomicAdd(dst + 2, v.z * invN);
        atomicAdd(dst + 3, v.w * invN);
    }
}

// ---------------------------------------------------------------------------
// c1: op0: Gt = G + G@R[p]   op1: W[p^1] = W[p] + R[p]^T @ W[p]
// grid (8,8): by -> op(1b) | rowtile(1b) | coltile(1b). 64x64 tile, 4x4 micro.
// Also zeroes g_R[p^1] for the next layer (2048 elems per block).
// ---------------------------------------------------------------------------
__global__ __launch_bounds__(256) void c1_kernel(int p) {
    const int b = blockIdx.x, d = blockIdx.y;
    const int op = d >> 2, rt = (d >> 1) & 1, ct = d & 1;
    const int i0 = rt * 64, c0 = ct * 64;
    const int tid = threadIdx.x, tx = tid & 15, ty = tid >> 4;
    __shared__ __align__(16) float As[2][16][64];
    __shared__ __align__(16) float Bs[2][16][64];

    const float* Rc = &g_R[p][b][0][0];
    const float* srcA = op ? Rc : &g_G[b][0][0];
    const float* srcB = op ? &g_W[p][b][0][0] : Rc;
    const float* base = op ? &g_W[p][b][0][0] : &g_G[b][0][0];
    float* dst = op ? &g_W[p ^ 1][b][0][0] : &g_Gt[b][0][0];

    const int sr = tid >> 4, sc = (tid & 15) * 4;

    float4 ra, rb;
    ra = *(const float4*)&srcA[(0 + sr) * DP1 + i0 + sc];
    rb = *(const float4*)&srcB[(0 + sr) * DP1 + c0 + sc];
    *(float4*)&As[0][sr][sc] = ra;
    *(float4*)&Bs[0][sr][sc] = rb;
    __syncthreads();

    float acc[4][4];
#pragma unroll
    for (int i = 0; i < 4; i++)
#pragma unroll
        for (int j = 0; j < 4; j++) acc[i][j] = 0.0f;

    for (int t = 0; t < 8; t++) {
        const int cur = t & 1;
        if (t < 7) {
            int k0 = (t + 1) * 16;
            ra = *(const float4*)&srcA[(k0 + sr) * DP1 + i0 + sc];
            rb = *(const float4*)&srcB[(k0 + sr) * DP1 + c0 + sc];
        }
#pragma unroll
        for (int kk = 0; kk < 16; kk++) {
            float4 av = *(const float4*)&As[cur][kk][ty * 4];
            float4 bv = *(const float4*)&Bs[cur][kk][tx * 4];
            float a_[4] = {av.x, av.y, av.z, av.w};
            float b_[4] = {bv.x, bv.y, bv.z, bv.w};
#pragma unroll
            for (int i = 0; i < 4; i++)
#pragma unroll
                for (int j = 0; j < 4; j++) acc[i][j] = fmaf(a_[i], b_[j], acc[i][j]);
        }
        if (t < 7) {
            const int nxt = cur ^ 1;
            *(float4*)&As[nxt][sr][sc] = ra;
            *(float4*)&Bs[nxt][sr][sc] = rb;
            __syncthreads();
        }
    }

#pragma unroll
    for (int i = 0; i < 4; i++) {
        int row = i0 + ty * 4 + i;
        float4 b4 = *(const float4*)&base[row * DP1 + c0 + tx * 4];
        float4 v = make_float4(b4.x + acc[i][0], b4.y + acc[i][1],
                               b4.z + acc[i][2], b4.w + acc[i][3]);
        *(float4*)&dst[row * DP1 + c0 + tx * 4] = v;
    }

    // zero next-parity R for the next layer's tr atomics (64 blocks -> 2048 each)
    {
        float* Rn = &g_R[p ^ 1][0][0][0];
        int blk = b * 8 + d;              // 0..63
#pragma unroll
        for (int k = 0; k < 8; k++)
            Rn[blk * 2048 + k * 256 + tid] = 0.0f;
    }
}

// ---------------------------------------------------------------------------
// c2: G = Gt + R[p]^T @ Gt.  grid (8,4): by -> rowtile | coltile.
// ---------------------------------------------------------------------------
__global__ __launch_bounds__(256) void c2_kernel(int p) {
    const int b = blockIdx.x, d = blockIdx.y;
    const int rt = d >> 1, ct = d & 1;
    const int i0 = rt * 64, c0 = ct * 64;
    const int tid = threadIdx.x, tx = tid & 15, ty = tid >> 4;
    __shared__ __align__(16) float As[2][16][64];
    __shared__ __align__(16) float Bs[2][16][64];

    const float* srcA = &g_R[p][b][0][0];
    const float* srcB = &g_Gt[b][0][0];

    const int sr = tid >> 4, sc = (tid & 15) * 4;

    float4 ra, rb;
    ra = *(const float4*)&srcA[(0 + sr) * DP1 + i0 + sc];
    rb = *(const float4*)&srcB[(0 + sr) * DP1 + c0 + sc];
    *(float4*)&As[0][sr][sc] = ra;
    *(float4*)&Bs[0][sr][sc] = rb;
    __syncthreads();

    float acc[4][4];
#pragma unroll
    for (int i = 0; i < 4; i++)
#pragma unroll
        for (int j = 0; j < 4; j++) acc[i][j] = 0.0f;

    for (int t = 0; t < 8; t++) {
        const int cur = t & 1;
        if (t < 7) {
            int k0 = (t + 1) * 16;
            ra = *(const float4*)&srcA[(k0 + sr) * DP1 + i0 + sc];
            rb = *(const float4*)&srcB[(k0 + sr) * DP1 + c0 + sc];
        }
#pragma unroll
        for (int kk = 0; kk < 16; kk++) {
            float4 av = *(const float4*)&As[cur][kk][ty * 4];
            float4 bv = *(const float4*)&Bs[cur][kk][tx * 4];
            float a_[4] = {av.x, av.y, av.z, av.w};
            float b_[4] = {bv.x, bv.y, bv.z, bv.w};
#pragma unroll
            for (int i = 0; i < 4; i++)
#pragma unroll
                for (int j = 0; j < 4; j++) acc[i][j] = fmaf(a_[i], b_[j], acc[i][j]);
        }
        if (t < 7) {
            const int nxt = cur ^ 1;
            *(float4*)&As[nxt][sr][sc] = ra;
            *(float4*)&Bs[nxt][sr][sc] = rb;
            __syncthreads();
        }
    }

    float* Gb = &g_G[b][0][0];
    const float* Gt = &g_Gt[b][0][0];
#pragma unroll
    for (int i = 0; i < 4; i++) {
        int row = i0 + ty * 4 + i;
        float4 b4 = *(const float4*)&Gt[row * DP1 + c0 + tx * 4];
        float4 v = make_float4(b4.x + acc[i][0], b4.y + acc[i][1],
                               b4.z + acc[i][2], b4.w + acc[i][3]);
        *(float4*)&Gb[row * DP1 + c0 + tx * 4] = v;
    }
}

// ---------------------------------------------------------------------------
// Final: Zout = Zin @ W^T  (identity inside W; W ends in g_W[NLAYER&1... p_final])
// ---------------------------------------------------------------------------
__global__ __launch_bounds__(256) void final_kernel(const float* __restrict__ Zin,
                                                    float* __restrict__ Zout,
                                                    int pw) {
    const int b = blockIdx.x, rt = blockIdx.y;
    const int n0 = rt * 64;
    const int tid = threadIdx.x, tx = tid & 15, ty = tid >> 4;
    __shared__ __align__(16) float As[2][16][68];
    __shared__ __align__(16) float Bs[2][16][132];

    const float* Zb = Zin + (size_t)b * NP1 * DP1;
    float* Zo = Zout + (size_t)b * NP1 * DP1;
    const float* Wb = &g_W[pw][b][0][0];

    const int arow = tid >> 2, aq = tid & 3;
    const int brow = tid >> 2, bq = tid & 3;

    float4 va, vb0, vb1;
    va  = *(const float4*)&Zb[(size_t)(n0 + arow) * DP1 + aq * 4];
    vb0 = *(const float4*)&Wb[brow * DP1 + bq * 4];
    vb1 = *(const float4*)&Wb[(brow + 64) * DP1 + bq * 4];
    {
        As[0][aq * 4 + 0][arow] = va.x;  As[0][aq * 4 + 1][arow] = va.y;
        As[0][aq * 4 + 2][arow] = va.z;  As[0][aq * 4 + 3][arow] = va.w;
        Bs[0][bq * 4 + 0][brow] = vb0.x; Bs[0][bq * 4 + 1][brow] = vb0.y;
        Bs[0][bq * 4 + 2][brow] = vb0.z; Bs[0][bq * 4 + 3][brow] = vb0.w;
        Bs[0][bq * 4 + 0][brow + 64] = vb1.x; Bs[0][bq * 4 + 1][brow + 64] = vb1.y;
        Bs[0][bq * 4 + 2][brow + 64] = vb1.z; Bs[0][bq * 4 + 3][brow + 64] = vb1.w;
    }
    __syncthreads();

    float acc[4][8];
#pragma unroll
    for (int i = 0; i < 4; i++)
#pragma unroll
        for (int j = 0; j < 8; j++) acc[i][j] = 0.0f;

    for (int t = 0; t < 8; t++) {
        const int cb = t & 1;
        if (t < 7) {
            int k0 = (t + 1) * 16;
            va  = *(const float4*)&Zb[(size_t)(n0 + arow) * DP1 + k0 + aq * 4];
            vb0 = *(const float4*)&Wb[brow * DP1 + k0 + bq * 4];
            vb1 = *(const float4*)&Wb[(brow + 64) * DP1 + k0 + bq * 4];
        }
#pragma unroll
        for (int kk = 0; kk < 16; kk++) {
            float4 av = *(const float4*)&As[cb][kk][ty * 4];
            float4 b0 = *(const float4*)&Bs[cb][kk][tx * 8];
            float4 b1 = *(const float4*)&Bs[cb][kk][tx * 8 + 4];
            float a_[4] = {av.x, av.y, av.z, av.w};
            float b_[8] = {b0.x, b0.y, b0.z, b0.w, b1.x, b1.y, b1.z, b1.w};
#pragma unroll
            for (int i = 0; i < 4; i++)
#pragma unroll
                for (int j = 0; j < 8; j++) acc[i][j] = fmaf(a_[i], b_[j], acc[i][j]);
        }
        if (t < 7) {
            const int nb2 = cb ^ 1;
            As[nb2][aq * 4 + 0][arow] = va.x;  As[nb2][aq * 4 + 1][arow] = va.y;
            As[nb2][aq * 4 + 2][arow] = va.z;  As[nb2][aq * 4 + 3][arow] = va.w;
            Bs[nb2][bq * 4 + 0][brow] = vb0.x; Bs[nb2][bq * 4 + 1][brow] = vb0.y;
            Bs[nb2][bq * 4 + 2][brow] = vb0.z; Bs[nb2][bq * 4 + 3][brow] = vb0.w;
            Bs[nb2][bq * 4 + 0][brow + 64] = vb1.x; Bs[nb2][bq * 4 + 1][brow + 64] = vb1.y;
            Bs[nb2][bq * 4 + 2][brow + 64] = vb1.z; Bs[nb2][bq * 4 + 3][brow + 64] = vb1.w;
            __syncthreads();
        }
    }

#pragma unroll
    for (int i = 0; i < 4; i++) {
        size_t off = (size_t)(n0 + ty * 4 + i) * DP1 + tx * 8;
        *(float4*)&Zo[off]     = make_float4(acc[i][0], acc[i][1], acc[i][2], acc[i][3]);
        *(float4*)&Zo[off + 4] = make_float4(acc[i][4], acc[i][5], acc[i][6], acc[i][7]);
    }
}

// ---------------------------------------------------------------------------
extern "C" void kernel_launch(void* const* d_in, const int* in_sizes, int n_in,
                              void* d_out, int out_size) {
    const float* Z_in     = (const float*)d_in[0];
    const float* allparam = (const float*)d_in[1];
    float* Z_out = (float*)d_out;

    pad_params_kernel<<<(NLAYER * NHEAD * DP1 * DP1 + 255) / 256, 256>>>(allparam);
    init_kernel<<<(BATCH * DP1 * DP1 + 255) / 256, 256>>>();
    gram_kernel<<<dim3(BATCH, 16), 256>>>(Z_in);

    for (int l = 0; l < NLAYER; l++) {
        int p = l & 1;
        tr_kernel<<<dim3(BATCH, NHEAD, 2), 256>>>(l, p);
        c1_kernel<<<dim3(BATCH, 8), 256>>>(p);
        if (l < NLAYER - 1)
            c2_kernel<<<dim3(BATCH, 4), 256>>>(p);
    }

    final_kernel<<<dim3(BATCH, 16), 256>>>(Z_in, Z_out, NLAYER & 1);
}

// round 7
// speedup vs baseline: 1.2835x; 1.2372x over previous
#include <cuda_runtime.h>
#include <mma.h>
using namespace nvcuda;

#define BATCH   8
#define NP1     1024
#define DP1     128
#define NLAYER  4
#define NHEAD   8
#define NTOK    1023
#define DSMALL  127

#define GS_LD   132     // padded ld for 128-col tf32 operand
#define BT_LD   68      // padded ld for 64-col operand
#define TR_SMEM ((DP1 * GS_LD + DP1 * BT_LD) * 4)   // 102400 B

// ---------------------------------------------------------------------------
// g_PB[l][h][a][b] = Pfull[b][a]   (P^T, padded; corner Pfull[127][127]=1)
// g_QT[l][h][k][i] = Qfull[i][k]   (Q^T, zero padded)
// g_G [b]      : Gram (symmetric), per layer G <- (I+R)^T G (I+R)
// g_Gt[b]      : Gtmp = G (I+R)
// g_R [p][b]   : R_l, layer-parity ping-pong (zeroed one layer ahead by c1)
// g_W [p][b]   : W = M^T ping-pong, W' = W + R^T W  (I included)
// ---------------------------------------------------------------------------
__device__ __align__(16) float g_PB[NLAYER][NHEAD][DP1][DP1];
__device__ __align__(16) float g_QT[NLAYER][NHEAD][DP1][DP1];
__device__ __align__(16) float g_G [BATCH][DP1][DP1];
__device__ __align__(16) float g_Gt[BATCH][DP1][DP1];
__device__ __align__(16) float g_R [2][BATCH][DP1][DP1];
__device__ __align__(16) float g_W [2][BATCH][DP1][DP1];

// ---------------------------------------------------------------------------
__global__ void pad_params_kernel(const float* __restrict__ allparam) {
    int idx = blockIdx.x * blockDim.x + threadIdx.x;
    const int total = NLAYER * NHEAD * DP1 * DP1;
    if (idx >= total) return;
    int bb = idx & 127;
    int a  = (idx >> 7) & 127;
    int h  = (idx >> 14) & 7;
    int l  = idx >> 17;

    float pv = 0.0f, qv = 0.0f;
    if (bb < DSMALL && a < DSMALL) {
        const float* base = allparam
            + ((((size_t)l * NHEAD + h) * 2 + 0) * DSMALL + bb) * DSMALL + a;
        pv = base[0];
        qv = base[DSMALL * DSMALL];
    }
    if (bb == DSMALL && a == DSMALL) pv = 1.0f;

    g_PB[l][h][a][bb] = pv;
    g_QT[l][h][a][bb] = qv;
}

__global__ void init_kernel() {
    int idx = blockIdx.x * blockDim.x + threadIdx.x;   // < 8*128*128
    int j = idx & 127, i = (idx >> 7) & 127, b = idx >> 14;
    g_G[b][i][j] = 0.0f;
    g_R[0][b][i][j] = 0.0f;
    g_W[0][b][i][j] = (i == j) ? 1.0f : 0.0f;
}

// ---------------------------------------------------------------------------
// Gram: G[b] += Zslab^T Zslab over rows [s*64, s*64+64) ∩ [0,1023)
// ---------------------------------------------------------------------------
__global__ __launch_bounds__(256) void gram_kernel(const float* __restrict__ Z) {
    const int b = blockIdx.x, s = blockIdx.y;
    const int tid = threadIdx.x, tx = tid & 15, ty = tid >> 4;
    __shared__ __align__(16) float Zs[64][DP1];

    const float* Zb = Z + (size_t)b * NP1 * DP1;
    const int m0 = s * 64;
#pragma unroll
    for (int q = 0; q < 8; q++) {
        int f = tid + q * 256;
        int row = f >> 5, c4 = f & 31;
        int m = m0 + row;
        float4 v = make_float4(0.f, 0.f, 0.f, 0.f);
        if (m < NTOK) v = *(const float4*)&Zb[(size_t)m * DP1 + c4 * 4];
        *(float4*)&Zs[row][c4 * 4] = v;
    }
    __syncthreads();

    float acc[8][8];
#pragma unroll
    for (int i = 0; i < 8; i++)
#pragma unroll
        for (int j = 0; j < 8; j++) acc[i][j] = 0.0f;

#pragma unroll 8
    for (int kk = 0; kk < 64; kk++) {
        float4 a0 = *(const float4*)&Zs[kk][ty * 8];
        float4 a1 = *(const float4*)&Zs[kk][ty * 8 + 4];
        float4 b0 = *(const float4*)&Zs[kk][tx * 8];
        float4 b1 = *(const float4*)&Zs[kk][tx * 8 + 4];
        float a_[8] = {a0.x, a0.y, a0.z, a0.w, a1.x, a1.y, a1.z, a1.w};
        float b_[8] = {b0.x, b0.y, b0.z, b0.w, b1.x, b1.y, b1.z, b1.w};
#pragma unroll
        for (int i = 0; i < 8; i++)
#pragma unroll
            for (int j = 0; j < 8; j++) acc[i][j] = fmaf(a_[i], b_[j], acc[i][j]);
    }

    float* Gb = &g_G[b][0][0];
#pragma unroll
    for (int i = 0; i < 8; i++)
#pragma unroll
        for (int j = 0; j < 8; j++)
            atomicAdd(&Gb[(ty * 8 + i) * DP1 + tx * 8 + j], acc[i][j]);
}

// ---------------------------------------------------------------------------
// Fused TR (tf32 wmma, smem-staged). Block (b, h, s): cols [s*64, s*64+64).
//   Phase 1: Ts = G[b] @ PB[:, slice]            (smem Gs x smem Bs -> smem Ts)
//   Phase 2: R[p][b][:, slice] += (1/N) Q @ Ts   (smem QTs x smem Ts -> atomic)
// 512 threads = 16 warps. Warp w: row band (w&7)*16, col tiles {(w>>3)*2, +1}.
// Dynamic smem 100KB: Gs[128][132] (G, then QT), BTs[128][68] (PB, then Ts).
// ---------------------------------------------------------------------------
__global__ __launch_bounds__(512)
void tr_kernel(int layer, int p) {
    extern __shared__ __align__(16) float dsm[];
    float* Gs  = dsm;                    // [128][132]
    float* BTs = dsm + DP1 * GS_LD;      // [128][68]

    const int b = blockIdx.x, h = blockIdx.y, s = blockIdx.z;
    const int c0 = s * 64;
    const int tid = threadIdx.x;
    const int w = tid >> 5;
    const int rw = (w & 7) * 16;         // row band
    const int jt = (w >> 3) * 32;        // col offset of first of 2 tiles

    const float* Gb = &g_G[b][0][0];
    const float* PB = &g_PB[layer][h][0][0];
    const float* QT = &g_QT[layer][h][0][0];

    // ---- stage G (tf32-rounded) and PB slice ----
#pragma unroll
    for (int q = 0; q < 8; q++) {
        int f = tid + q * 512;               // 0..4095 float4 of G
        int row = f >> 5, c4 = (f & 31) * 4;
        float4 v = *(const float4*)&Gb[row * DP1 + c4];
        v.x = wmma::__float_to_tf32(v.x);  v.y = wmma::__float_to_tf32(v.y);
        v.z = wmma::__float_to_tf32(v.z);  v.w = wmma::__float_to_tf32(v.w);
        *(float4*)&Gs[row * GS_LD + c4] = v;
    }
#pragma unroll
    for (int q = 0; q < 4; q++) {
        int f = tid + q * 512;               // 0..2047 float4 of PB slice
        int row = f >> 4, c4 = (f & 15) * 4;
        float4 v = *(const float4*)&PB[row * DP1 + c0 + c4];
        v.x = wmma::__float_to_tf32(v.x);  v.y = wmma::__float_to_tf32(v.y);
        v.z = wmma::__float_to_tf32(v.z);  v.w = wmma::__float_to_tf32(v.w);
        *(float4*)&BTs[row * BT_LD + c4] = v;
    }
    __syncthreads();

    // ---- Phase 1: C = G @ PBs ----
    wmma::fragment<wmma::accumulator, 16, 16, 8, float> c0f, c1f;
    wmma::fill_fragment(c0f, 0.0f);
    wmma::fill_fragment(c1f, 0.0f);
#pragma unroll
    for (int k0 = 0; k0 < DP1; k0 += 8) {
        wmma::fragment<wmma::matrix_a, 16, 16, 8, wmma::precision::tf32,
                       wmma::row_major> a;
        wmma::load_matrix_sync(a, Gs + rw * GS_LD + k0, GS_LD);
        wmma::fragment<wmma::matrix_b, 16, 16, 8, wmma::precision::tf32,
                       wmma::row_major> b0, b1;
        wmma::load_matrix_sync(b0, BTs + k0 * BT_LD + jt, BT_LD);
        wmma::load_matrix_sync(b1, BTs + k0 * BT_LD + jt + 16, BT_LD);
        wmma::mma_sync(c0f, a, b0, c0f);
        wmma::mma_sync(c1f, a, b1, c1f);
    }
    __syncthreads();   // all Gs/BTs reads done

    // ---- Ts -> BTs; QT -> Gs ----
    wmma::store_matrix_sync(BTs + rw * BT_LD + jt, c0f, BT_LD, wmma::mem_row_major);
    wmma::store_matrix_sync(BTs + rw * BT_LD + jt + 16, c1f, BT_LD, wmma::mem_row_major);
#pragma unroll
    for (int q = 0; q < 8; q++) {
        int f = tid + q * 512;
        int row = f >> 5, c4 = (f & 31) * 4;
        float4 v = *(const float4*)&QT[row * DP1 + c4];
        v.x = wmma::__float_to_tf32(v.x);  v.y = wmma::__float_to_tf32(v.y);
        v.z = wmma::__float_to_tf32(v.z);  v.w = wmma::__float_to_tf32(v.w);
        *(float4*)&Gs[row * GS_LD + c4] = v;
    }
    __syncthreads();
    // round Ts in place (128 x 64 -> 2048 float4)
#pragma unroll
    for (int q = 0; q < 4; q++) {
        int f = tid + q * 512;
        int row = f >> 4, c4 = (f & 15) * 4;
        float4 v = *(const float4*)&BTs[row * BT_LD + c4];
        v.x = wmma::__float_to_tf32(v.x);  v.y = wmma::__float_to_tf32(v.y);
        v.z = wmma::__float_to_tf32(v.z);  v.w = wmma::__float_to_tf32(v.w);
        *(float4*)&BTs[row * BT_LD + c4] = v;
    }
    __syncthreads();

    // ---- Phase 2: C = Q @ Ts   (A[i][k] = QTs[k][i] -> col_major) ----
    wmma::fill_fragment(c0f, 0.0f);
    wmma::fill_fragment(c1f, 0.0f);
#pragma unroll
    for (int k0 = 0; k0 < DP1; k0 += 8) {
        wmma::fragment<wmma::matrix_a, 16, 16, 8, wmma::precision::tf32,
                       wmma::col_major> a;
        wmma::load_matrix_sync(a, Gs + k0 * GS_LD + rw, GS_LD);
        wmma::fragment<wmma::matrix_b, 16, 16, 8, wmma::precision::tf32,
                       wmma::row_major> b0, b1;
        wmma::load_matrix_sync(b0, BTs + k0 * BT_LD + jt, BT_LD);
        wmma::load_matrix_sync(b1, BTs + k0 * BT_LD + jt + 16, BT_LD);
        wmma::mma_sync(c0f, a, b0, c0f);
        wmma::mma_sync(c1f, a, b1, c1f);
    }
    __syncthreads();   // all Ts reads done; reuse BTs for result
    wmma::store_matrix_sync(BTs + rw * BT_LD + jt, c0f, BT_LD, wmma::mem_row_major);
    wmma::store_matrix_sync(BTs + rw * BT_LD + jt + 16, c1f, BT_LD, wmma::mem_row_major);
    __syncthreads();

    // ---- atomic accumulate into g_R[p][b][:, slice] ----
    const float invN = 1.0f / (float)NTOK;
    float* Rb = &g_R[p][b][0][0];
#pragma unroll
    for (int q = 0; q < 4; q++) {
        int f = tid + q * 512;               // 0..2047 float4
        int row = f >> 4, c4 = (f & 15) * 4;
        float4 v = *(const float4*)&BTs[row * BT_LD + c4];
        float* dst = &Rb[row * DP1 + c0 + c4];
        atomicAdd(dst + 0, v.x * invN);
        atomicAdd(dst + 1, v.y * invN);
        atomicAdd(dst + 2, v.z * invN);
        atomicAdd(dst + 3, v.w * invN);
    }
}

// ---------------------------------------------------------------------------
// c1: op0: Gt = G + G@R[p]   op1: W[p^1] = W[p] + R[p]^T @ W[p]
// grid (8,8). 64x64 tile, 4x4 micro. Also zeroes g_R[p^1] for next layer.
// ---------------------------------------------------------------------------
__global__ __launch_bounds__(256) void c1_kernel(int p) {
    const int b = blockIdx.x, d = blockIdx.y;
    const int op = d >> 2, rt = (d >> 1) & 1, ct = d & 1;
    const int i0 = rt * 64, c0 = ct * 64;
    const int tid = threadIdx.x, tx = tid & 15, ty = tid >> 4;
    __shared__ __align__(16) float As[2][16][64];
    __shared__ __align__(16) float Bs[2][16][64];

    const float* Rc = &g_R[p][b][0][0];
    const float* srcA = op ? Rc : &g_G[b][0][0];
    const float* srcB = op ? &g_W[p][b][0][0] : Rc;
    const float* base = op ? &g_W[p][b][0][0] : &g_G[b][0][0];
    float* dst = op ? &g_W[p ^ 1][b][0][0] : &g_Gt[b][0][0];

    const int sr = tid >> 4, sc = (tid & 15) * 4;

    float4 ra, rb;
    ra = *(const float4*)&srcA[(0 + sr) * DP1 + i0 + sc];
    rb = *(const float4*)&srcB[(0 + sr) * DP1 + c0 + sc];
    *(float4*)&As[0][sr][sc] = ra;
    *(float4*)&Bs[0][sr][sc] = rb;
    __syncthreads();

    float acc[4][4];
#pragma unroll
    for (int i = 0; i < 4; i++)
#pragma unroll
        for (int j = 0; j < 4; j++) acc[i][j] = 0.0f;

    for (int t = 0; t < 8; t++) {
        const int cur = t & 1;
        if (t < 7) {
            int k0 = (t + 1) * 16;
            ra = *(const float4*)&srcA[(k0 + sr) * DP1 + i0 + sc];
            rb = *(const float4*)&srcB[(k0 + sr) * DP1 + c0 + sc];
        }
#pragma unroll
        for (int kk = 0; kk < 16; kk++) {
            float4 av = *(const float4*)&As[cur][kk][ty * 4];
            float4 bv = *(const float4*)&Bs[cur][kk][tx * 4];
            float a_[4] = {av.x, av.y, av.z, av.w};
            float b_[4] = {bv.x, bv.y, bv.z, bv.w};
#pragma unroll
            for (int i = 0; i < 4; i++)
#pragma unroll
                for (int j = 0; j < 4; j++) acc[i][j] = fmaf(a_[i], b_[j], acc[i][j]);
        }
        if (t < 7) {
            const int nxt = cur ^ 1;
            *(float4*)&As[nxt][sr][sc] = ra;
            *(float4*)&Bs[nxt][sr][sc] = rb;
            __syncthreads();
        }
    }

#pragma unroll
    for (int i = 0; i < 4; i++) {
        int row = i0 + ty * 4 + i;
        float4 b4 = *(const float4*)&base[row * DP1 + c0 + tx * 4];
        float4 v = make_float4(b4.x + acc[i][0], b4.y + acc[i][1],
                               b4.z + acc[i][2], b4.w + acc[i][3]);
        *(float4*)&dst[row * DP1 + c0 + tx * 4] = v;
    }

    // zero next-parity R for the next layer's tr atomics
    {
        float* Rn = &g_R[p ^ 1][0][0][0];
        int blk = b * 8 + d;              // 0..63
#pragma unroll
        for (int k = 0; k < 8; k++)
            Rn[blk * 2048 + k * 256 + tid] = 0.0f;
    }
}

// ---------------------------------------------------------------------------
// c2: G = Gt + R[p]^T @ Gt.  grid (8,4).
// ---------------------------------------------------------------------------
__global__ __launch_bounds__(256) void c2_kernel(int p) {
    const int b = blockIdx.x, d = blockIdx.y;
    const int rt = d >> 1, ct = d & 1;
    const int i0 = rt * 64, c0 = ct * 64;
    const int tid = threadIdx.x, tx = tid & 15, ty = tid >> 4;
    __shared__ __align__(16) float As[2][16][64];
    __shared__ __align__(16) float Bs[2][16][64];

    const float* srcA = &g_R[p][b][0][0];
    const float* srcB = &g_Gt[b][0][0];

    const int sr = tid >> 4, sc = (tid & 15) * 4;

    float4 ra, rb;
    ra = *(const float4*)&srcA[(0 + sr) * DP1 + i0 + sc];
    rb = *(const float4*)&srcB[(0 + sr) * DP1 + c0 + sc];
    *(float4*)&As[0][sr][sc] = ra;
    *(float4*)&Bs[0][sr][sc] = rb;
    __syncthreads();

    float acc[4][4];
#pragma unroll
    for (int i = 0; i < 4; i++)
#pragma unroll
        for (int j = 0; j < 4; j++) acc[i][j] = 0.0f;

    for (int t = 0; t < 8; t++) {
        const int cur = t & 1;
        if (t < 7) {
            int k0 = (t + 1) * 16;
            ra = *(const float4*)&srcA[(k0 + sr) * DP1 + i0 + sc];
            rb = *(const float4*)&srcB[(k0 + sr) * DP1 + c0 + sc];
        }
#pragma unroll
        for (int kk = 0; kk < 16; kk++) {
            float4 av = *(const float4*)&As[cur][kk][ty * 4];
            float4 bv = *(const float4*)&Bs[cur][kk][tx * 4];
            float a_[4] = {av.x, av.y, av.z, av.w};
            float b_[4] = {bv.x, bv.y, bv.z, bv.w};
#pragma unroll
            for (int i = 0; i < 4; i++)
#pragma unroll
                for (int j = 0; j < 4; j++) acc[i][j] = fmaf(a_[i], b_[j], acc[i][j]);
        }
        if (t < 7) {
            const int nxt = cur ^ 1;
            *(float4*)&As[nxt][sr][sc] = ra;
            *(float4*)&Bs[nxt][sr][sc] = rb;
            __syncthreads();
        }
    }

    float* Gb = &g_G[b][0][0];
    const float* Gt = &g_Gt[b][0][0];
#pragma unroll
    for (int i = 0; i < 4; i++) {
        int row = i0 + ty * 4 + i;
        float4 b4 = *(const float4*)&Gt[row * DP1 + c0 + tx * 4];
        float4 v = make_float4(b4.x + acc[i][0], b4.y + acc[i][1],
                               b4.z + acc[i][2], b4.w + acc[i][3]);
        *(float4*)&Gb[row * DP1 + c0 + tx * 4] = v;
    }
}

// ---------------------------------------------------------------------------
// Final: Zout = Zin @ W^T  (identity inside W)
// ---------------------------------------------------------------------------
__global__ __launch_bounds__(256) void final_kernel(const float* __restrict__ Zin,
                                                    float* __restrict__ Zout,
                                                    int pw) {
    const int b = blockIdx.x, rt = blockIdx.y;
    const int n0 = rt * 64;
    const int tid = threadIdx.x, tx = tid & 15, ty = tid >> 4;
    __shared__ __align__(16) float As[2][16][68];
    __shared__ __align__(16) float Bs[2][16][132];

    const float* Zb = Zin + (size_t)b * NP1 * DP1;
    float* Zo = Zout + (size_t)b * NP1 * DP1;
    const float* Wb = &g_W[pw][b][0][0];

    const int arow = tid >> 2, aq = tid & 3;
    const int brow = tid >> 2, bq = tid & 3;

    float4 va, vb0, vb1;
    va  = *(const float4*)&Zb[(size_t)(n0 + arow) * DP1 + aq * 4];
    vb0 = *(const float4*)&Wb[brow * DP1 + bq * 4];
    vb1 = *(const float4*)&Wb[(brow + 64) * DP1 + bq * 4];
    {
        As[0][aq * 4 + 0][arow] = va.x;  As[0][aq * 4 + 1][arow] = va.y;
        As[0][aq * 4 + 2][arow] = va.z;  As[0][aq * 4 + 3][arow] = va.w;
        Bs[0][bq * 4 + 0][brow] = vb0.x; Bs[0][bq * 4 + 1][brow] = vb0.y;
        Bs[0][bq * 4 + 2][brow] = vb0.z; Bs[0][bq * 4 + 3][brow] = vb0.w;
        Bs[0][bq * 4 + 0][brow + 64] = vb1.x; Bs[0][bq * 4 + 1][brow + 64] = vb1.y;
        Bs[0][bq * 4 + 2][brow + 64] = vb1.z; Bs[0][bq * 4 + 3][brow + 64] = vb1.w;
    }
    __syncthreads();

    float acc[4][8];
#pragma unroll
    for (int i = 0; i < 4; i++)
#pragma unroll
        for (int j = 0; j < 8; j++) acc[i][j] = 0.0f;

    for (int t = 0; t < 8; t++) {
        const int cb = t & 1;
        if (t < 7) {
            int k0 = (t + 1) * 16;
            va  = *(const float4*)&Zb[(size_t)(n0 + arow) * DP1 + k0 + aq * 4];
            vb0 = *(const float4*)&Wb[brow * DP1 + k0 + bq * 4];
            vb1 = *(const float4*)&Wb[(brow + 64) * DP1 + k0 + bq * 4];
        }
#pragma unroll
        for (int kk = 0; kk < 16; kk++) {
            float4 av = *(const float4*)&As[cb][kk][ty * 4];
            float4 b0 = *(const float4*)&Bs[cb][kk][tx * 8];
            float4 b1 = *(const float4*)&Bs[cb][kk][tx * 8 + 4];
            float a_[4] = {av.x, av.y, av.z, av.w};
            float b_[8] = {b0.x, b0.y, b0.z, b0.w, b1.x, b1.y, b1.z, b1.w};
#pragma unroll
            for (int i = 0; i < 4; i++)
#pragma unroll
                for (int j = 0; j < 8; j++) acc[i][j] = fmaf(a_[i], b_[j], acc[i][j]);
        }
        if (t < 7) {
            const int nb2 = cb ^ 1;
            As[nb2][aq * 4 + 0][arow] = va.x;  As[nb2][aq * 4 + 1][arow] = va.y;
            As[nb2][aq * 4 + 2][arow] = va.z;  As[nb2][aq * 4 + 3][arow] = va.w;
            Bs[nb2][bq * 4 + 0][brow] = vb0.x; Bs[nb2][bq * 4 + 1][brow] = vb0.y;
            Bs[nb2][bq * 4 + 2][brow] = vb0.z; Bs[nb2][bq * 4 + 3][brow] = vb0.w;
            Bs[nb2][bq * 4 + 0][brow + 64] = vb1.x; Bs[nb2][bq * 4 + 1][brow + 64] = vb1.y;
            Bs[nb2][bq * 4 + 2][brow + 64] = vb1.z; Bs[nb2][bq * 4 + 3][brow + 64] = vb1.w;
            __syncthreads();
        }
    }

#pragma unroll
    for (int i = 0; i < 4; i++) {
        size_t off = (size_t)(n0 + ty * 4 + i) * DP1 + tx * 8;
        *(float4*)&Zo[off]     = make_float4(acc[i][0], acc[i][1], acc[i][2], acc[i][3]);
        *(float4*)&Zo[off + 4] = make_float4(acc[i][4], acc[i][5], acc[i][6], acc[i][7]);
    }
}

// ---------------------------------------------------------------------------
extern "C" void kernel_launch(void* const* d_in, const int* in_sizes, int n_in,
                              void* d_out, int out_size) {
    const float* Z_in     = (const float*)d_in[0];
    const float* allparam = (const float*)d_in[1];
    float* Z_out = (float*)d_out;

    cudaFuncSetAttribute(tr_kernel,
                         cudaFuncAttributeMaxDynamicSharedMemorySize, TR_SMEM);

    pad_params_kernel<<<(NLAYER * NHEAD * DP1 * DP1 + 255) / 256, 256>>>(allparam);
    init_kernel<<<(BATCH * DP1 * DP1 + 255) / 256, 256>>>();
    gram_kernel<<<dim3(BATCH, 16), 256>>>(Z_in);

    for (int l = 0; l < NLAYER; l++) {
        int p = l & 1;
        tr_kernel<<<dim3(BATCH, NHEAD, 2), 512, TR_SMEM>>>(l, p);
        c1_kernel<<<dim3(BATCH, 8), 256>>>(p);
        if (l < NLAYER - 1)
            c2_kernel<<<dim3(BATCH, 4), 256>>>(p);
    }

    final_kernel<<<dim3(BATCH, 16), 256>>>(Z_in, Z_out, NLAYER & 1);
}

// round 8
// speedup vs baseline: 1.3550x; 1.0557x over previous
#include <cuda_runtime.h>
#include <mma.h>
using namespace nvcuda;

#define BATCH   8
#define NP1     1024
#define DP1     128
#define NLAYER  4
#define NHEAD   8
#define NTOK    1023
#define DSMALL  127

#define LD128   132     // padded ld for 128-col tf32 operand
#define LD64    68      // padded ld for 64-col operand

// tr: Gs[128][132] + Qs[128][132] + Ps[128][68] + Ts[128][68]
#define TR_SMEM   ((2 * DP1 * LD128 + 2 * DP1 * LD64) * 4)       // 204800
// gram: Zs[64][132] + Cs[128][132]
#define GRAM_SMEM ((64 * LD128 + DP1 * LD128) * 4)               // 101376
// final: Zs[128][132] + Es[128][132]
#define FIN_SMEM  ((2 * DP1 * LD128) * 4)                        // 135168

// ---------------------------------------------------------------------------
// g_PB[l][h][a][b] = Pfull[b][a]   (P^T, padded; corner Pfull[127][127]=1)
// g_QT[l][h][k][i] = Qfull[i][k]   (Q^T, zero padded)
// g_G [b]      : Gram (symmetric), per layer G <- (I+R)^T G (I+R)
// g_Gt[b]      : Gtmp = G (I+R)
// g_R [p][b]   : R_l ping-pong (zeroed one layer ahead by c1; R[0] by init)
// g_W [p][b]   : W = M^T ping-pong (I included)
// ---------------------------------------------------------------------------
__device__ __align__(16) float g_PB[NLAYER][NHEAD][DP1][DP1];
__device__ __align__(16) float g_QT[NLAYER][NHEAD][DP1][DP1];
__device__ __align__(16) float g_G [BATCH][DP1][DP1];
__device__ __align__(16) float g_Gt[BATCH][DP1][DP1];
__device__ __align__(16) float g_R [2][BATCH][DP1][DP1];
__device__ __align__(16) float g_W [2][BATCH][DP1][DP1];

__device__ __forceinline__ float4 tf32x4(float4 v) {
    v.x = wmma::__float_to_tf32(v.x);  v.y = wmma::__float_to_tf32(v.y);
    v.z = wmma::__float_to_tf32(v.z);  v.w = wmma::__float_to_tf32(v.w);
    return v;
}

// ---------------------------------------------------------------------------
__global__ void pad_params_kernel(const float* __restrict__ allparam) {
    int idx = blockIdx.x * blockDim.x + threadIdx.x;
    const int total = NLAYER * NHEAD * DP1 * DP1;
    if (idx >= total) return;
    int bb = idx & 127;
    int a  = (idx >> 7) & 127;
    int h  = (idx >> 14) & 7;
    int l  = idx >> 17;

    float pv = 0.0f, qv = 0.0f;
    if (bb < DSMALL && a < DSMALL) {
        const float* base = allparam
            + ((((size_t)l * NHEAD + h) * 2 + 0) * DSMALL + bb) * DSMALL + a;
        pv = base[0];
        qv = base[DSMALL * DSMALL];
    }
    if (bb == DSMALL && a == DSMALL) pv = 1.0f;

    g_PB[l][h][a][bb] = pv;
    g_QT[l][h][a][bb] = qv;
}

__global__ void init_kernel() {
    int idx = blockIdx.x * blockDim.x + threadIdx.x;   // < 8*128*128
    int j = idx & 127, i = (idx >> 7) & 127, b = idx >> 14;
    g_G[b][i][j] = 0.0f;
    g_R[0][b][i][j] = 0.0f;
    g_W[0][b][i][j] = (i == j) ? 1.0f : 0.0f;
}

// ---------------------------------------------------------------------------
// Gram (tf32 wmma): G[b] += Zslab^T Zslab, slab rows [s*64, s*64+64) ∩ [0,1023)
// grid (8,16), 512 thr. Warp w: row band (w&7)*16, col tiles (w>>3)*64 (+4x16).
// ---------------------------------------------------------------------------
__global__ __launch_bounds__(512)
void gram_kernel(const float* __restrict__ Z) {
    extern __shared__ __align__(16) float dsm[];
    float* Zs = dsm;                 // [64][132]
    float* Cs = dsm + 64 * LD128;    // [128][132]

    const int b = blockIdx.x, s = blockIdx.y;
    const int tid = threadIdx.x;
    const int w = tid >> 5;
    const int rw = (w & 7) * 16;
    const int jt = (w >> 3) * 64;

    const float* Zb = Z + (size_t)b * NP1 * DP1;
    const int m0 = s * 64;

    // stage slab, tf32-rounded, masked
#pragma unroll
    for (int q = 0; q < 4; q++) {
        int f = tid + q * 512;                 // 0..2047 f4
        int row = f >> 5, c4 = (f & 31) * 4;
        float4 v = make_float4(0.f, 0.f, 0.f, 0.f);
        if (m0 + row < NTOK)
            v = tf32x4(*(const float4*)&Zb[(size_t)(m0 + row) * DP1 + c4]);
        *(float4*)&Zs[row * LD128 + c4] = v;
    }
    __syncthreads();

    wmma::fragment<wmma::accumulator, 16, 16, 8, float> c[4];
#pragma unroll
    for (int j = 0; j < 4; j++) wmma::fill_fragment(c[j], 0.0f);

#pragma unroll
    for (int k0 = 0; k0 < 64; k0 += 8) {
        wmma::fragment<wmma::matrix_a, 16, 16, 8, wmma::precision::tf32,
                       wmma::col_major> a;     // A[i][k] = Z[k][rw+i]
        wmma::load_matrix_sync(a, Zs + k0 * LD128 + rw, LD128);
#pragma unroll
        for (int j = 0; j < 4; j++) {
            wmma::fragment<wmma::matrix_b, 16, 16, 8, wmma::precision::tf32,
                           wmma::row_major> bf;
            wmma::load_matrix_sync(bf, Zs + k0 * LD128 + jt + j * 16, LD128);
            wmma::mma_sync(c[j], a, bf, c[j]);
        }
    }
#pragma unroll
    for (int j = 0; j < 4; j++)
        wmma::store_matrix_sync(Cs + rw * LD128 + jt + j * 16, c[j], LD128,
                                wmma::mem_row_major);
    __syncthreads();

    float* Gb = &g_G[b][0][0];
#pragma unroll
    for (int q = 0; q < 8; q++) {
        int f = tid + q * 512;                 // 0..4095 f4
        int row = f >> 5, c4 = (f & 31) * 4;
        float4 v = *(const float4*)&Cs[row * LD128 + c4];
        float* dst = &Gb[row * DP1 + c4];
        atomicAdd(dst + 0, v.x);
        atomicAdd(dst + 1, v.y);
        atomicAdd(dst + 2, v.z);
        atomicAdd(dst + 3, v.w);
    }
}

// ---------------------------------------------------------------------------
// Fused TR (tf32 wmma, single-stage smem). Block (b, h, s): cols [s*64,+64).
// All operands resident: Gs + Qs + Ps + Ts = 205KB. 3 syncs total.
//   Phase 1: Ts = G @ PBslice   (acc regs rounded to tf32 on store)
//   Phase 2: C  = Q @ Ts; R[p][b][:, slice] += C/N  (atomic)
// 512 thr; warp w: rows (w&7)*16, cols (w>>3)*32 (2 tiles of 16).
// ---------------------------------------------------------------------------
__global__ __launch_bounds__(512)
void tr_kernel(int layer, int p) {
    extern __shared__ __align__(16) float dsm[];
    float* Gs = dsm;                              // [128][132]
    float* Qs = dsm + DP1 * LD128;                // [128][132]
    float* Ps = dsm + 2 * DP1 * LD128;            // [128][68]
    float* Ts = dsm + 2 * DP1 * LD128 + DP1 * LD64; // [128][68]

    const int b = blockIdx.x, h = blockIdx.y, s = blockIdx.z;
    const int c0 = s * 64;
    const int tid = threadIdx.x;
    const int w = tid >> 5;
    const int rw = (w & 7) * 16;
    const int jt = (w >> 3) * 32;

    const float* Gb = &g_G[b][0][0];
    const float* PB = &g_PB[layer][h][0][0];
    const float* QT = &g_QT[layer][h][0][0];

    // ---- stage everything once ----
#pragma unroll
    for (int q = 0; q < 8; q++) {
        int f = tid + q * 512;                 // 0..4095 f4
        int row = f >> 5, c4 = (f & 31) * 4;
        *(float4*)&Gs[row * LD128 + c4] =
            tf32x4(*(const float4*)&Gb[row * DP1 + c4]);
        *(float4*)&Qs[row * LD128 + c4] =
            tf32x4(*(const float4*)&QT[row * DP1 + c4]);
    }
#pragma unroll
    for (int q = 0; q < 4; q++) {
        int f = tid + q * 512;                 // 0..2047 f4
        int row = f >> 4, c4 = (f & 15) * 4;
        *(float4*)&Ps[row * LD64 + c4] =
            tf32x4(*(const float4*)&PB[row * DP1 + c0 + c4]);
    }
    __syncthreads();

    // ---- Phase 1: Ts = G @ Ps ----
    wmma::fragment<wmma::accumulator, 16, 16, 8, float> c0f, c1f;
    wmma::fill_fragment(c0f, 0.0f);
    wmma::fill_fragment(c1f, 0.0f);
#pragma unroll
    for (int k0 = 0; k0 < DP1; k0 += 8) {
        wmma::fragment<wmma::matrix_a, 16, 16, 8, wmma::precision::tf32,
                       wmma::row_major> a;
        wmma::load_matrix_sync(a, Gs + rw * LD128 + k0, LD128);
        wmma::fragment<wmma::matrix_b, 16, 16, 8, wmma::precision::tf32,
                       wmma::row_major> b0, b1;
        wmma::load_matrix_sync(b0, Ps + k0 * LD64 + jt, LD64);
        wmma::load_matrix_sync(b1, Ps + k0 * LD64 + jt + 16, LD64);
        wmma::mma_sync(c0f, a, b0, c0f);
        wmma::mma_sync(c1f, a, b1, c1f);
    }
    // round accumulators in registers (no extra smem pass)
#pragma unroll
    for (int t = 0; t < c0f.num_elements; t++) {
        c0f.x[t] = wmma::__float_to_tf32(c0f.x[t]);
        c1f.x[t] = wmma::__float_to_tf32(c1f.x[t]);
    }
    wmma::store_matrix_sync(Ts + rw * LD64 + jt, c0f, LD64, wmma::mem_row_major);
    wmma::store_matrix_sync(Ts + rw * LD64 + jt + 16, c1f, LD64, wmma::mem_row_major);
    __syncthreads();

    // ---- Phase 2: C = Q @ Ts   (A[i][k] = Qs[k*132+i] -> col_major) ----
    wmma::fill_fragment(c0f, 0.0f);
    wmma::fill_fragment(c1f, 0.0f);
#pragma unroll
    for (int k0 = 0; k0 < DP1; k0 += 8) {
        wmma::fragment<wmma::matrix_a, 16, 16, 8, wmma::precision::tf32,
                       wmma::col_major> a;
        wmma::load_matrix_sync(a, Qs + k0 * LD128 + rw, LD128);
        wmma::fragment<wmma::matrix_b, 16, 16, 8, wmma::precision::tf32,
                       wmma::row_major> b0, b1;
        wmma::load_matrix_sync(b0, Ts + k0 * LD64 + jt, LD64);
        wmma::load_matrix_sync(b1, Ts + k0 * LD64 + jt + 16, LD64);
        wmma::mma_sync(c0f, a, b0, c0f);
        wmma::mma_sync(c1f, a, b1, c1f);
    }
    __syncthreads();   // Ps dead only after phase-1; Ts reads done; reuse Ps for C
    wmma::store_matrix_sync(Ps + rw * LD64 + jt, c0f, LD64, wmma::mem_row_major);
    wmma::store_matrix_sync(Ps + rw * LD64 + jt + 16, c1f, LD64, wmma::mem_row_major);
    __syncthreads();

    // ---- atomic accumulate ----
    const float invN = 1.0f / (float)NTOK;
    float* Rb = &g_R[p][b][0][0];
#pragma unroll
    for (int q = 0; q < 4; q++) {
        int f = tid + q * 512;                 // 0..2047 f4
        int row = f >> 4, c4 = (f & 15) * 4;
        float4 v = *(const float4*)&Ps[row * LD64 + c4];
        float* dst = &Rb[row * DP1 + c0 + c4];
        atomicAdd(dst + 0, v.x * invN);
        atomicAdd(dst + 1, v.y * invN);
        atomicAdd(dst + 2, v.z * invN);
        atomicAdd(dst + 3, v.w * invN);
    }
}

// ---------------------------------------------------------------------------
// c1: op0: Gt = G + G@R[p]   op1: W[p^1] = W[p] + R[p]^T @ W[p]
// grid (8,8). 64x64 tile, 4x4 micro. Also zeroes g_R[p^1] for next layer.
// ---------------------------------------------------------------------------
__global__ __launch_bounds__(256) void c1_kernel(int p) {
    const int b = blockIdx.x, d = blockIdx.y;
    const int op = d >> 2, rt = (d >> 1) & 1, ct = d & 1;
    const int i0 = rt * 64, c0 = ct * 64;
    const int tid = threadIdx.x, tx = tid & 15, ty = tid >> 4;
    __shared__ __align__(16) float As[2][16][64];
    __shared__ __align__(16) float Bs[2][16][64];

    const float* Rc = &g_R[p][b][0][0];
    const float* srcA = op ? Rc : &g_G[b][0][0];
    const float* srcB = op ? &g_W[p][b][0][0] : Rc;
    const float* base = op ? &g_W[p][b][0][0] : &g_G[b][0][0];
    float* dst = op ? &g_W[p ^ 1][b][0][0] : &g_Gt[b][0][0];

    const int sr = tid >> 4, sc = (tid & 15) * 4;

    float4 ra, rb;
    ra = *(const float4*)&srcA[(0 + sr) * DP1 + i0 + sc];
    rb = *(const float4*)&srcB[(0 + sr) * DP1 + c0 + sc];
    *(float4*)&As[0][sr][sc] = ra;
    *(float4*)&Bs[0][sr][sc] = rb;
    __syncthreads();

    float acc[4][4];
#pragma unroll
    for (int i = 0; i < 4; i++)
#pragma unroll
        for (int j = 0; j < 4; j++) acc[i][j] = 0.0f;

    for (int t = 0; t < 8; t++) {
        const int cur = t & 1;
        if (t < 7) {
            int k0 = (t + 1) * 16;
            ra = *(const float4*)&srcA[(k0 + sr) * DP1 + i0 + sc];
            rb = *(const float4*)&srcB[(k0 + sr) * DP1 + c0 + sc];
        }
#pragma unroll
        for (int kk = 0; kk < 16; kk++) {
            float4 av = *(const float4*)&As[cur][kk][ty * 4];
            float4 bv = *(const float4*)&Bs[cur][kk][tx * 4];
            float a_[4] = {av.x, av.y, av.z, av.w};
            float b_[4] = {bv.x, bv.y, bv.z, bv.w};
#pragma unroll
            for (int i = 0; i < 4; i++)
#pragma unroll
                for (int j = 0; j < 4; j++) acc[i][j] = fmaf(a_[i], b_[j], acc[i][j]);
        }
        if (t < 7) {
            const int nxt = cur ^ 1;
            *(float4*)&As[nxt][sr][sc] = ra;
            *(float4*)&Bs[nxt][sr][sc] = rb;
            __syncthreads();
        }
    }

#pragma unroll
    for (int i = 0; i < 4; i++) {
        int row = i0 + ty * 4 + i;
        float4 b4 = *(const float4*)&base[row * DP1 + c0 + tx * 4];
        float4 v = make_float4(b4.x + acc[i][0], b4.y + acc[i][1],
                               b4.z + acc[i][2], b4.w + acc[i][3]);
        *(float4*)&dst[row * DP1 + c0 + tx * 4] = v;
    }

    // zero next-parity R for the next layer's tr atomics
    {
        float* Rn = &g_R[p ^ 1][0][0][0];
        int blk = b * 8 + d;              // 0..63
#pragma unroll
        for (int k = 0; k < 8; k++)
            Rn[blk * 2048 + k * 256 + tid] = 0.0f;
    }
}

// ---------------------------------------------------------------------------
// c2: G = Gt + R[p]^T @ Gt.  grid (8,4).
// ---------------------------------------------------------------------------
__global__ __launch_bounds__(256) void c2_kernel(int p) {
    const int b = blockIdx.x, d = blockIdx.y;
    const int rt = d >> 1, ct = d & 1;
    const int i0 = rt * 64, c0 = ct * 64;
    const int tid = threadIdx.x, tx = tid & 15, ty = tid >> 4;
    __shared__ __align__(16) float As[2][16][64];
    __shared__ __align__(16) float Bs[2][16][64];

    const float* srcA = &g_R[p][b][0][0];
    const float* srcB = &g_Gt[b][0][0];

    const int sr = tid >> 4, sc = (tid & 15) * 4;

    float4 ra, rb;
    ra = *(const float4*)&srcA[(0 + sr) * DP1 + i0 + sc];
    rb = *(const float4*)&srcB[(0 + sr) * DP1 + c0 + sc];
    *(float4*)&As[0][sr][sc] = ra;
    *(float4*)&Bs[0][sr][sc] = rb;
    __syncthreads();

    float acc[4][4];
#pragma unroll
    for (int i = 0; i < 4; i++)
#pragma unroll
        for (int j = 0; j < 4; j++) acc[i][j] = 0.0f;

    for (int t = 0; t < 8; t++) {
        const int cur = t & 1;
        if (t < 7) {
            int k0 = (t + 1) * 16;
            ra = *(const float4*)&srcA[(k0 + sr) * DP1 + i0 + sc];
            rb = *(const float4*)&srcB[(k0 + sr) * DP1 + c0 + sc];
        }
#pragma unroll
        for (int kk = 0; kk < 16; kk++) {
            float4 av = *(const float4*)&As[cur][kk][ty * 4];
            float4 bv = *(const float4*)&Bs[cur][kk][tx * 4];
            float a_[4] = {av.x, av.y, av.z, av.w};
            float b_[4] = {bv.x, bv.y, bv.z, bv.w};
#pragma unroll
            for (int i = 0; i < 4; i++)
#pragma unroll
                for (int j = 0; j < 4; j++) acc[i][j] = fmaf(a_[i], b_[j], acc[i][j]);
        }
        if (t < 7) {
            const int nxt = cur ^ 1;
            *(float4*)&As[nxt][sr][sc] = ra;
            *(float4*)&Bs[nxt][sr][sc] = rb;
            __syncthreads();
        }
    }

    float* Gb = &g_G[b][0][0];
    const float* Gt = &g_Gt[b][0][0];
#pragma unroll
    for (int i = 0; i < 4; i++) {
        int row = i0 + ty * 4 + i;
        float4 b4 = *(const float4*)&Gt[row * DP1 + c0 + tx * 4];
        float4 v = make_float4(b4.x + acc[i][0], b4.y + acc[i][1],
                               b4.z + acc[i][2], b4.w + acc[i][3]);
        *(float4*)&Gb[row * DP1 + c0 + tx * 4] = v;
    }
}

// ---------------------------------------------------------------------------
// Final (tf32 wmma on correction): Zout = Zin + Zin @ E^T, E = W[pw] - I.
// grid (8,8): 128-row tiles. 512 thr; warp w: rows (w&7)*16, cols (w>>3)*64.
// ---------------------------------------------------------------------------
__global__ __launch_bounds__(512)
void final_kernel(const float* __restrict__ Zin, float* __restrict__ Zout,
                  int pw) {
    extern __shared__ __align__(16) float dsm[];
    float* Zs = dsm;                 // [128][132] (Z tf32; later C fp32)
    float* Es = dsm + DP1 * LD128;   // [128][132]

    const int b = blockIdx.x, rt = blockIdx.y;
    const int n0 = rt * 128;
    const int tid = threadIdx.x;
    const int w = tid >> 5;
    const int rw = (w & 7) * 16;
    const int jt = (w >> 3) * 64;

    const float* Zb = Zin + (size_t)b * NP1 * DP1;
    float* Zo = Zout + (size_t)b * NP1 * DP1;
    const float* Wb = &g_W[pw][b][0][0];

    // stage Z rows (tf32) and E = W - I (tf32)
#pragma unroll
    for (int q = 0; q < 8; q++) {
        int f = tid + q * 512;                 // 0..4095 f4
        int row = f >> 5, c4 = (f & 31) * 4;
        *(float4*)&Zs[row * LD128 + c4] =
            tf32x4(*(const float4*)&Zb[(size_t)(n0 + row) * DP1 + c4]);
        float4 e = *(const float4*)&Wb[row * DP1 + c4];
        if (row >= c4 && row < c4 + 4) {
            if (row == c4)     e.x -= 1.0f;
            else if (row == c4 + 1) e.y -= 1.0f;
            else if (row == c4 + 2) e.z -= 1.0f;
            else               e.w -= 1.0f;
        }
        *(float4*)&Es[row * LD128 + c4] = tf32x4(e);
    }
    __syncthreads();

    wmma::fragment<wmma::accumulator, 16, 16, 8, float> c[4];
#pragma unroll
    for (int j = 0; j < 4; j++) wmma::fill_fragment(c[j], 0.0f);

#pragma unroll
    for (int k0 = 0; k0 < DP1; k0 += 8) {
        wmma::fragment<wmma::matrix_a, 16, 16, 8, wmma::precision::tf32,
                       wmma::row_major> a;
        wmma::load_matrix_sync(a, Zs + rw * LD128 + k0, LD128);
#pragma unroll
        for (int j = 0; j < 4; j++) {
            // B[k][i] = E[i][k] -> col_major over Es, ld 132
            wmma::fragment<wmma::matrix_b, 16, 16, 8, wmma::precision::tf32,
                           wmma::col_major> bf;
            wmma::load_matrix_sync(bf, Es + (jt + j * 16) * LD128 + k0, LD128);
            wmma::mma_sync(c[j], a, bf, c[j]);
        }
    }
    __syncthreads();   // all Zs reads done; reuse Zs for C
#pragma unroll
    for (int j = 0; j < 4; j++)
        wmma::store_matrix_sync(Zs + rw * LD128 + jt + j * 16, c[j], LD128,
                                wmma::mem_row_major);
    __syncthreads();

    // Zout = Zin (fp32 reload) + C
#pragma unroll
    for (int q = 0; q < 8; q++) {
        int f = tid + q * 512;
        int row = f >> 5, c4 = (f & 31) * 4;
        size_t off = (size_t)(n0 + row) * DP1 + c4;
        float4 z = *(const float4*)&Zb[off];
        float4 cc = *(const float4*)&Zs[row * LD128 + c4];
        *(float4*)&Zo[off] =
            make_float4(z.x + cc.x, z.y + cc.y, z.z + cc.z, z.w + cc.w);
    }
}

// ---------------------------------------------------------------------------
extern "C" void kernel_launch(void* const* d_in, const int* in_sizes, int n_in,
                              void* d_out, int out_size) {
    const float* Z_in     = (const float*)d_in[0];
    const float* allparam = (const float*)d_in[1];
    float* Z_out = (float*)d_out;

    cudaFuncSetAttribute(tr_kernel,
                         cudaFuncAttributeMaxDynamicSharedMemorySize, TR_SMEM);
    cudaFuncSetAttribute(gram_kernel,
                         cudaFuncAttributeMaxDynamicSharedMemorySize, GRAM_SMEM);
    cudaFuncSetAttribute(final_kernel,
                         cudaFuncAttributeMaxDynamicSharedMemorySize, FIN_SMEM);

    pad_params_kernel<<<(NLAYER * NHEAD * DP1 * DP1 + 255) / 256, 256>>>(allparam);
    init_kernel<<<(BATCH * DP1 * DP1 + 255) / 256, 256>>>();
    gram_kernel<<<dim3(BATCH, 16), 512, GRAM_SMEM>>>(Z_in);

    for (int l = 0; l < NLAYER; l++) {
        int p = l & 1;
        tr_kernel<<<dim3(BATCH, NHEAD, 2), 512, TR_SMEM>>>(l, p);
        c1_kernel<<<dim3(BATCH, 8), 256>>>(p);
        if (l < NLAYER - 1)
            c2_kernel<<<dim3(BATCH, 4), 256>>>(p);
    }

    final_kernel<<<dim3(BATCH, 8), 512, FIN_SMEM>>>(Z_in, Z_out, NLAYER & 1);
}